// round 2
// baseline (speedup 1.0000x reference)
#include <cuda_runtime.h>
#include <math.h>

// ---------------- problem constants ----------------
#define BB    8
#define DIM   128
#define TT    16
#define HH    32
#define WW    32
#define INNER 256
#define NHEAD 4
#define DHEAD 64
#define SEQ   16
#define MTOT  131072          // B*T*H*W rows, m = ((b*T+t)*H+h)*W+w
#define LD    258             // padded smem row stride (bank-conflict avoidance)

// ---------------- scratch (device globals; no allocs) ----------------
__device__ float g_up[(size_t)MTOT * 512];   // up-projection output [M,512] (x_m | z)
__device__ float g_hs[(size_t)MTOT * 256];   // h_state [M,256]

// =====================================================================
// Kernel 1: up projection GEMM  up[m,n] = sum_k xs[m,k] * W_up[k,n]
//   A gathered from x[b,c,t,h,w]; rows of a 64-tile share (b,t), hw contiguous
// =====================================================================
__global__ __launch_bounds__(256) void k_up(const float* __restrict__ x,
                                            const float* __restrict__ Wup)
{
    extern __shared__ float sm[];
    float* As = sm;             // [128][64]
    float* Bs = sm + 128 * 64;  // [128][64]

    const int tid = threadIdx.x;
    const int n0 = blockIdx.x * 64;
    const int m0 = blockIdx.y * 64;
    const int hw0 = m0 & 1023;
    const int bt  = m0 >> 10;           // b*16 + t
    const float* xb = x + (size_t)(bt >> 4) * 2097152 + (size_t)(bt & 15) * 1024 + hw0;

    const int r = tid & 63, kk = tid >> 6;     // r: row/col within 64, kk: 0..3
#pragma unroll
    for (int p = 0; p < 32; p++) {
        int k = kk * 32 + p;
        As[k * 64 + r] = xb[(size_t)k * 16384 + r];     // x[b,k,t,hw0+r]
        Bs[k * 64 + r] = Wup[k * 512 + n0 + r];
    }
    __syncthreads();

    const int tx = tid & 15, ty = tid >> 4;    // tx: n micro, ty: m micro
    float acc[4][4] = {};
#pragma unroll 8
    for (int k = 0; k < 128; k++) {
        float4 a4 = *(const float4*)(As + (k << 6) + (ty << 2));
        float4 b4 = *(const float4*)(Bs + (k << 6) + (tx << 2));
        float av[4] = {a4.x, a4.y, a4.z, a4.w};
        float bv[4] = {b4.x, b4.y, b4.z, b4.w};
#pragma unroll
        for (int i = 0; i < 4; i++)
#pragma unroll
            for (int j = 0; j < 4; j++) acc[i][j] += av[i] * bv[j];
    }

    float* ob = g_up + (size_t)(m0 + ty * 4) * 512 + n0 + tx * 4;
#pragma unroll
    for (int i = 0; i < 4; i++) {
        float4 v = make_float4(acc[i][0], acc[i][1], acc[i][2], acc[i][3]);
        *(float4*)(ob + (size_t)i * 512) = v;
    }
}

// =====================================================================
// Kernel 2: fused conv/qkv/gates/mLSTM/LN/gating, one CTA per sequence
// =====================================================================
struct SM2 {
    float xm[SEQ * LD];
    float xc[SEQ * LD];
    float qb[SEQ * LD];     // q; reused later for ht / normalized ht
    float kb[SEQ * LD];
    float vb[SEQ * LD];
    float chat[NHEAD * SEQ * SEQ];
    float lf[NHEAD * 17];
    float igv[SEQ * NHEAD];
    float fgv[SEQ * NHEAD];
    float gpart[2 * SEQ * 16 * NHEAD];   // [ig/fg][t][p][h]
};

__device__ __forceinline__ float siluf(float x) { return x / (1.f + expf(-x)); }

__global__ __launch_bounds__(256) void k_mid(
    const float* __restrict__ cw,  const float* __restrict__ cb,
    const float* __restrict__ Wq,  const float* __restrict__ Wk,
    const float* __restrict__ Wv,
    const float* __restrict__ igw, const float* __restrict__ igb,
    const float* __restrict__ fgw, const float* __restrict__ fgb,
    const float* __restrict__ lnw, const float* __restrict__ skip)
{
    extern __shared__ char smraw[];
    SM2& s = *reinterpret_cast<SM2*>(smraw);
    const int tid = threadIdx.x;
    const int seq = blockIdx.x;
    const int b = seq >> 10, hw = seq & 1023;

    // ---- P0: load x_m rows ----
#pragma unroll
    for (int p = 0; p < 16; p++) {
        int t = p, c = tid;  // 256 threads cover one 256-wide row per pass
        s.xm[t * LD + c] = g_up[(size_t)(((b * 16 + t) << 10) + hw) * 512 + c];
    }
    __syncthreads();

    // ---- P1: causal depthwise conv + silu ----
#pragma unroll
    for (int p = 0; p < 16; p++) {
        int t = p, c = tid;
        float acc = cb[c];
#pragma unroll
        for (int j = 0; j < 4; j++) {
            int tt = t - 3 + j;
            if (tt >= 0) acc += cw[j * 256 + c] * s.xm[tt * LD + c];
        }
        s.xc[t * LD + c] = siluf(acc);
    }
    __syncthreads();

    // ---- P2: block-diagonal q, k, v ----
#pragma unroll 4
    for (int p = 0; p < 16; p++) {
        int t = p, c = tid;
        int nb = c >> 2, o = c & 3;
        const float* xcr = &s.xc[t * LD + nb * 4];
        const float* xmr = &s.xm[t * LD + nb * 4];
        float aq = 0.f, ak = 0.f, av = 0.f;
#pragma unroll
        for (int i = 0; i < 4; i++) {
            int wi = (nb * 4 + o) * 4 + i;
            aq += Wq[wi] * xcr[i];
            ak += Wk[wi] * xcr[i];
            av += Wv[wi] * xmr[i];
        }
        s.qb[t * LD + c] = aq;
        s.kb[t * LD + c] = ak;
        s.vb[t * LD + c] = av;
    }
    __syncthreads();

    // ---- P3: ig/fg gate pre-activations (split-K over 16 parts of 48) ----
    {
        int t = tid >> 4, p = tid & 15;
        float ai[4] = {0, 0, 0, 0}, af[4] = {0, 0, 0, 0};
        const float* qr = &s.qb[t * LD];
        const float* kr = &s.kb[t * LD];
        const float* vr = &s.vb[t * LD];
        int i0 = p * 48;
        for (int i = i0; i < i0 + 48; i++) {
            float val = (i < 256) ? qr[i] : (i < 512) ? kr[i - 256] : vr[i - 512];
            float4 wi = *(const float4*)(igw + i * 4);
            float4 wf = *(const float4*)(fgw + i * 4);
            ai[0] += val * wi.x; ai[1] += val * wi.y; ai[2] += val * wi.z; ai[3] += val * wi.w;
            af[0] += val * wf.x; af[1] += val * wf.y; af[2] += val * wf.z; af[3] += val * wf.w;
        }
#pragma unroll
        for (int h = 0; h < 4; h++) {
            s.gpart[((0 * 16 + t) * 16 + p) * 4 + h] = ai[h];
            s.gpart[((1 * 16 + t) * 16 + p) * 4 + h] = af[h];
        }
    }
    __syncthreads();
    if (tid < 64) {
        int t = tid >> 2, h = tid & 3;
        float si = 0.f, sf = 0.f;
        for (int p = 0; p < 16; p++) {
            si += s.gpart[((0 * 16 + t) * 16 + p) * 4 + h];
            sf += s.gpart[((1 * 16 + t) * 16 + p) * 4 + h];
        }
        s.igv[t * 4 + h] = si + igb[h];
        s.fgv[t * 4 + h] = sf + fgb[h];
    }
    __syncthreads();

    // ---- P4: cumulative log-sigmoid of forget gates (serial per head) ----
    if (tid < 4) {
        int h = tid;
        float run = 0.f;
        s.lf[h * 17 + 0] = 0.f;
        for (int t = 0; t < 16; t++) {
            float xg = s.fgv[t * 4 + h];
            float ls = (xg >= 0.f) ? -log1pf(expf(-xg)) : (xg - log1pf(expf(xg)));
            run += ls;
            s.lf[h * 17 + t + 1] = run;
        }
    }
    __syncthreads();

    // ---- P5: qk, gate matrix D, normalizer, Chat (per head: 64 threads, 2x2 tiles) ----
    {
        int head = tid >> 6, w = tid & 63;
        int s0 = (w >> 3) * 2;     // 2 query rows
        int t0 = (w & 7) * 2;      // 2 key cols
        float qk[2][2] = {};
        const float* q0 = &s.qb[(s0 + 0) * LD + head * 64];
        const float* q1 = &s.qb[(s0 + 1) * LD + head * 64];
        const float* k0 = &s.kb[(t0 + 0) * LD + head * 64];
        const float* k1 = &s.kb[(t0 + 1) * LD + head * 64];
#pragma unroll 8
        for (int d = 0; d < 64; d++) {
            float a0 = q0[d], a1 = q1[d], b0 = k0[d], b1 = k1[d];
            qk[0][0] += a0 * b0; qk[0][1] += a0 * b1;
            qk[1][0] += a1 * b0; qk[1][1] += a1 * b1;
        }
        float logD[2][2], mymax[2];
#pragma unroll
        for (int si = 0; si < 2; si++) {
            int ss = s0 + si;
            mymax[si] = -INFINITY;
#pragma unroll
            for (int tj = 0; tj < 2; tj++) {
                int t_ = t0 + tj;
                float v = (t_ <= ss)
                    ? (s.lf[head * 17 + ss + 1] - s.lf[head * 17 + t_ + 1] + s.igv[t_ * 4 + head])
                    : -INFINITY;
                logD[si][tj] = v;
                mymax[si] = fmaxf(mymax[si], v);
            }
        }
#pragma unroll
        for (int off = 1; off < 8; off <<= 1) {
            mymax[0] = fmaxf(mymax[0], __shfl_xor_sync(0xffffffffu, mymax[0], off));
            mymax[1] = fmaxf(mymax[1], __shfl_xor_sync(0xffffffffu, mymax[1], off));
        }
        float Cc[2][2], rowsum[2] = {0.f, 0.f};
#pragma unroll
        for (int si = 0; si < 2; si++)
#pragma unroll
            for (int tj = 0; tj < 2; tj++) {
                float Dv = expf(logD[si][tj] - mymax[si]);   // exp(-inf)=0 for masked
                float Cv = qk[si][tj] * 0.125f * Dv;
                Cc[si][tj] = Cv;
                rowsum[si] += Cv;
            }
#pragma unroll
        for (int off = 1; off < 8; off <<= 1) {
            rowsum[0] += __shfl_xor_sync(0xffffffffu, rowsum[0], off);
            rowsum[1] += __shfl_xor_sync(0xffffffffu, rowsum[1], off);
        }
#pragma unroll
        for (int si = 0; si < 2; si++) {
            float norm = fmaxf(fabsf(rowsum[si]), expf(-mymax[si]));
            float inv = 1.f / (norm + 1e-6f);
#pragma unroll
            for (int tj = 0; tj < 2; tj++)
                s.chat[(head * 16 + s0 + si) * 16 + t0 + tj] = Cc[si][tj] * inv;
        }
    }
    __syncthreads();

    // ---- P6: ht = Chat @ v   (written into qb) ----
#pragma unroll 2
    for (int p = 0; p < 16; p++) {
        int t_ = p, c = tid;
        int head = c >> 6;
        const float* ch = &s.chat[(head * 16 + t_) * 16];
        float acc = 0.f;
#pragma unroll
        for (int u = 0; u < 16; u++) acc += ch[u] * s.vb[u * LD + c];
        s.qb[t_ * LD + c] = acc;
    }
    __syncthreads();

    // ---- P7: multi-head layernorm (weight only) in place ----
    {
        int g = tid >> 2, p = tid & 3;      // 4 lanes per (s,head) group
        int sidx = g >> 2, head = g & 3;
        float* row = &s.qb[sidx * LD + head * 64 + p * 16];
        float sum = 0.f, sq = 0.f;
#pragma unroll
        for (int d = 0; d < 16; d++) { float v = row[d]; sum += v; sq += v * v; }
#pragma unroll
        for (int off = 1; off < 4; off <<= 1) {
            sum += __shfl_xor_sync(0xffffffffu, sum, off);
            sq  += __shfl_xor_sync(0xffffffffu, sq,  off);
        }
        float mu = sum * (1.f / 64.f);
        float var = sq * (1.f / 64.f) - mu * mu;
        float rstd = rsqrtf(var + 1e-5f);
        const float* lw = lnw + head * 64 + p * 16;
#pragma unroll
        for (int d = 0; d < 16; d++) row[d] = (row[d] - mu) * rstd * lw[d];
    }
    __syncthreads();

    // ---- P8: h_state = (hn + skip*xc) * silu(z); write to scratch ----
#pragma unroll
    for (int p = 0; p < 16; p++) {
        int t = p, c = tid;
        size_t m = (size_t)(((b * 16 + t) << 10) + hw);
        float z = g_up[m * 512 + 256 + c];
        float hs = (s.qb[t * LD + c] + skip[c] * s.xc[t * LD + c]) * siluf(z);
        g_hs[m * 256 + c] = hs;
    }
}

// =====================================================================
// Kernel 3: down projection GEMM, out[b,c,t,h,w] = h_state[m,:] @ W_down
// =====================================================================
__global__ __launch_bounds__(256) void k_down(const float* __restrict__ Wd,
                                              float* __restrict__ out)
{
    extern __shared__ float sm[];
    float* As = sm;            // [64 k][65 m] padded
    float* Bs = sm + 64 * 65;  // [64 k][128 n]

    const int tid = threadIdx.x;
    const int m0 = blockIdx.x * 64;
    const int mx = tid & 15, ny = tid >> 4;
    float acc[4][8] = {};

    for (int kc = 0; kc < 256; kc += 64) {
        {
            int kx = tid & 63, my = tid >> 6;
#pragma unroll
            for (int p = 0; p < 16; p++) {
                int m = p * 4 + my;
                As[kx * 65 + m] = g_hs[(size_t)(m0 + m) * 256 + kc + kx];
            }
            int nx = tid & 127, ky = tid >> 7;
#pragma unroll
            for (int p = 0; p < 32; p++) {
                int k = p * 2 + ky;
                Bs[k * 128 + nx] = Wd[(kc + k) * 128 + nx];
            }
        }
        __syncthreads();
#pragma unroll 4
        for (int k = 0; k < 64; k++) {
            float a[4];
#pragma unroll
            for (int i = 0; i < 4; i++) a[i] = As[k * 65 + mx + 16 * i];
            float4 b0 = *(const float4*)(Bs + k * 128 + ny * 8);
            float4 b1 = *(const float4*)(Bs + k * 128 + ny * 8 + 4);
            float bv[8] = {b0.x, b0.y, b0.z, b0.w, b1.x, b1.y, b1.z, b1.w};
#pragma unroll
            for (int i = 0; i < 4; i++)
#pragma unroll
                for (int j = 0; j < 8; j++) acc[i][j] += a[i] * bv[j];
        }
        __syncthreads();
    }

    const int hw0 = m0 & 1023;
    const int bt = m0 >> 10;
    float* ob = out + (size_t)(bt >> 4) * 2097152 + (size_t)(bt & 15) * 1024 + hw0;
#pragma unroll
    for (int j = 0; j < 8; j++)
#pragma unroll
        for (int i = 0; i < 4; i++)
            ob[(size_t)(ny * 8 + j) * 16384 + mx + 16 * i] = acc[i][j];
}

// =====================================================================
// launch
// =====================================================================
extern "C" void kernel_launch(void* const* d_in, const int* in_sizes, int n_in,
                              void* d_out, int out_size)
{
    const float* x    = (const float*)d_in[0];
    const float* Wup  = (const float*)d_in[1];
    const float* cw   = (const float*)d_in[2];
    const float* cb   = (const float*)d_in[3];
    const float* Wq   = (const float*)d_in[4];
    const float* Wk   = (const float*)d_in[5];
    const float* Wv   = (const float*)d_in[6];
    const float* igw  = (const float*)d_in[7];
    const float* igb  = (const float*)d_in[8];
    const float* fgw  = (const float*)d_in[9];
    const float* fgb  = (const float*)d_in[10];
    const float* lnw  = (const float*)d_in[11];
    const float* skip = (const float*)d_in[12];
    const float* Wd   = (const float*)d_in[13];
    float* out = (float*)d_out;

    (void)in_sizes; (void)n_in; (void)out_size;

    const int smem_up   = 128 * 64 * 2 * (int)sizeof(float);        // 64 KB
    const int smem_mid  = (int)sizeof(SM2);                          // ~95 KB
    const int smem_down = (64 * 65 + 64 * 128) * (int)sizeof(float); // ~48.3 KB

    cudaFuncSetAttribute(k_up,   cudaFuncAttributeMaxDynamicSharedMemorySize, smem_up);
    cudaFuncSetAttribute(k_mid,  cudaFuncAttributeMaxDynamicSharedMemorySize, smem_mid);
    cudaFuncSetAttribute(k_down, cudaFuncAttributeMaxDynamicSharedMemorySize, smem_down);

    k_up<<<dim3(8, 2048), 256, smem_up>>>(x, Wup);
    k_mid<<<8192, 256, smem_mid>>>(cw, cb, Wq, Wk, Wv, igw, igb, fgw, fgb, lnw, skip);
    k_down<<<2048, 256, smem_down>>>(Wd, out);
}

// round 7
// speedup vs baseline: 1.5857x; 1.5857x over previous
#include <cuda_runtime.h>
#include <math.h>

// ---------------- problem constants ----------------
#define MTOT  131072          // B*T*H*W rows, m = ((b*T+t)*H+h)*W+w
#define QLD   772             // qkv smem row stride (floats): mult of 4 (float4), !=0 mod 32

// ---------------- scratch (device globals; no allocs) ----------------
__device__ float g_up[(size_t)MTOT * 512];   // up-projection output [M,512] (x_m | z)
__device__ float g_hs[(size_t)MTOT * 256];   // h_state [M,256]

__device__ __forceinline__ float siluf(float x) { return x / (1.f + __expf(-x)); }

// =====================================================================
// Kernel 1: up projection GEMM  up[m,n] = sum_k xs[m,k] * W_up[k,n]
//   128x128 tile, 8x8 micro, kc=64
// =====================================================================
__global__ __launch_bounds__(256) void k_up(const float* __restrict__ x,
                                            const float* __restrict__ Wup)
{
    extern __shared__ float sm[];
    float* As = sm;             // [64 k][128 m]
    float* Bs = sm + 64 * 128;  // [64 k][128 n]

    const int tid = threadIdx.x;
    const int n0 = blockIdx.x * 128;
    const int m0 = blockIdx.y * 128;
    const int hw0 = m0 & 1023;
    const int bt  = m0 >> 10;           // b*16 + t
    const float* xb = x + (size_t)(bt >> 4) * 2097152 + (size_t)(bt & 15) * 1024 + hw0;

    const int mx = tid & 15, ny = tid >> 4;
    const int l4 = (tid & 31) * 4, kr = tid >> 5;  // loader coords

    float acc[8][8];
#pragma unroll
    for (int i = 0; i < 8; i++)
#pragma unroll
        for (int j = 0; j < 8; j++) acc[i][j] = 0.f;

    for (int kc = 0; kc < 128; kc += 64) {
#pragma unroll
        for (int p = 0; p < 8; p++) {
            int k = kr + p * 8;
            *(float4*)(As + k * 128 + l4) = *(const float4*)(xb + (size_t)(kc + k) * 16384 + l4);
            *(float4*)(Bs + k * 128 + l4) = *(const float4*)(Wup + (size_t)(kc + k) * 512 + n0 + l4);
        }
        __syncthreads();
#pragma unroll 4
        for (int k = 0; k < 64; k++) {
            float4 a0 = *(const float4*)(As + k * 128 + mx * 4);
            float4 a1 = *(const float4*)(As + k * 128 + 64 + mx * 4);
            float4 b0 = *(const float4*)(Bs + k * 128 + ny * 4);
            float4 b1 = *(const float4*)(Bs + k * 128 + 64 + ny * 4);
            float av[8] = {a0.x, a0.y, a0.z, a0.w, a1.x, a1.y, a1.z, a1.w};
            float bv[8] = {b0.x, b0.y, b0.z, b0.w, b1.x, b1.y, b1.z, b1.w};
#pragma unroll
            for (int i = 0; i < 8; i++)
#pragma unroll
                for (int j = 0; j < 8; j++) acc[i][j] += av[i] * bv[j];
        }
        __syncthreads();
    }

#pragma unroll
    for (int i = 0; i < 8; i++) {
        int m = m0 + mx * 4 + (i & 3) + ((i >> 2) << 6);
        float* ob = g_up + (size_t)m * 512 + n0;
        *(float4*)(ob + ny * 4)      = make_float4(acc[i][0], acc[i][1], acc[i][2], acc[i][3]);
        *(float4*)(ob + 64 + ny * 4) = make_float4(acc[i][4], acc[i][5], acc[i][6], acc[i][7]);
    }
}

// =====================================================================
// Kernel 2: fused conv/qkv/gates/mLSTM/LN/gating, one CTA per sequence
//   t-dimension register-resident; q/k/v via intra-warp shuffles
// =====================================================================
struct SM2 {
    float qkv[16 * QLD];        // per t: q[0,256) k[256,512) v[512,768)
    float chat[4 * 16 * 16];
    float lf[4 * 17];
    float igv[64];
    float fgv[64];
    float red[2 * 8 * 16];      // [sum|sq][warp][t]
};

__global__ __launch_bounds__(256) void k_mid(
    const float* __restrict__ cw,  const float* __restrict__ cb,
    const float* __restrict__ Wq,  const float* __restrict__ Wk,
    const float* __restrict__ Wv,
    const float* __restrict__ igw, const float* __restrict__ igb,
    const float* __restrict__ fgw, const float* __restrict__ fgb,
    const float* __restrict__ lnw, const float* __restrict__ skip)
{
    extern __shared__ char smraw[];
    SM2& s = *reinterpret_cast<SM2*>(smraw);
    const int tid  = threadIdx.x;
    const int lane = tid & 31;
    const int warp = tid >> 5;
    const int seq = blockIdx.x;
    const int b = seq >> 10, hw = seq & 1023;
    const size_t rowbase = ((size_t)(b * 16) << 10) + hw;   // + (t<<10) per step

    // ---- A: load x_m, conv+silu, q/k/v via shuffles; all t in registers ----
    float xm[16], xc[16];
#pragma unroll
    for (int t = 0; t < 16; t++)
        xm[t] = g_up[(rowbase + ((size_t)t << 10)) * 512 + tid];

    {
        float c0 = cw[tid], c1 = cw[256 + tid], c2 = cw[512 + tid], c3 = cw[768 + tid];
        float cbv = cb[tid];
#pragma unroll
        for (int t = 0; t < 16; t++) {
            float a = cbv + c3 * xm[t];
            if (t >= 1) a += c2 * xm[t - 1];
            if (t >= 2) a += c1 * xm[t - 2];
            if (t >= 3) a += c0 * xm[t - 3];
            xc[t] = siluf(a);
        }
    }

    {
        float4 wq = *(const float4*)(Wq + 4 * tid);
        float4 wk = *(const float4*)(Wk + 4 * tid);
        float4 wv = *(const float4*)(Wv + 4 * tid);
        int bl = lane & ~3;
#pragma unroll
        for (int t = 0; t < 16; t++) {
            float x0 = __shfl_sync(0xffffffffu, xc[t], bl);
            float x1 = __shfl_sync(0xffffffffu, xc[t], bl + 1);
            float x2 = __shfl_sync(0xffffffffu, xc[t], bl + 2);
            float x3 = __shfl_sync(0xffffffffu, xc[t], bl + 3);
            float m0v = __shfl_sync(0xffffffffu, xm[t], bl);
            float m1v = __shfl_sync(0xffffffffu, xm[t], bl + 1);
            float m2v = __shfl_sync(0xffffffffu, xm[t], bl + 2);
            float m3v = __shfl_sync(0xffffffffu, xm[t], bl + 3);
            float q = wq.x * x0 + wq.y * x1 + wq.z * x2 + wq.w * x3;
            float k = wk.x * x0 + wk.y * x1 + wk.z * x2 + wk.w * x3;
            float v = wv.x * m0v + wv.y * m1v + wv.z * m2v + wv.w * m3v;
            s.qkv[t * QLD + tid]       = q;
            s.qkv[t * QLD + 256 + tid] = k;
            s.qkv[t * QLD + 512 + tid] = v;
        }
    }
    __syncthreads();

    // ---- gates: ig/fg [t,h] over 768 inputs; 16 lanes split-K + shfl reduce ----
    {
        int t = tid >> 4, p = tid & 15;
        const float* row = s.qkv + t * QLD;
        float ai[4] = {0.f, 0.f, 0.f, 0.f}, af[4] = {0.f, 0.f, 0.f, 0.f};
#pragma unroll
        for (int ii = 0; ii < 12; ii++) {
            int idx = p * 4 + ii * 64;
            float4 xv = *(const float4*)(row + idx);
            float vals[4] = {xv.x, xv.y, xv.z, xv.w};
#pragma unroll
            for (int e = 0; e < 4; e++) {
                float val = vals[e];
                float4 wi = *(const float4*)(igw + (idx + e) * 4);
                float4 wf = *(const float4*)(fgw + (idx + e) * 4);
                ai[0] += val * wi.x; ai[1] += val * wi.y; ai[2] += val * wi.z; ai[3] += val * wi.w;
                af[0] += val * wf.x; af[1] += val * wf.y; af[2] += val * wf.z; af[3] += val * wf.w;
            }
        }
#pragma unroll
        for (int off = 1; off < 16; off <<= 1) {
#pragma unroll
            for (int h = 0; h < 4; h++) {
                ai[h] += __shfl_xor_sync(0xffffffffu, ai[h], off);
                af[h] += __shfl_xor_sync(0xffffffffu, af[h], off);
            }
        }
        if (p == 0) {
#pragma unroll
            for (int h = 0; h < 4; h++) {
                s.igv[t * 4 + h] = ai[h] + igb[h];
                s.fgv[t * 4 + h] = af[h] + fgb[h];
            }
        }
    }
    __syncthreads();

    // ---- cumulative log-sigmoid of forget gates (4 threads) ----
    if (tid < 4) {
        int h = tid;
        float run = 0.f;
        s.lf[h * 17 + 0] = 0.f;
#pragma unroll
        for (int t = 0; t < 16; t++) {
            float xg = s.fgv[t * 4 + h];
            float ls = fminf(xg, 0.f) - log1pf(__expf(-fabsf(xg)));
            run += ls;
            s.lf[h * 17 + t + 1] = run;
        }
    }
    __syncthreads();

    // ---- qk + gate matrix + normalizer -> chat (per head: 64 thr, 2x2 tiles) ----
    {
        int head = tid >> 6, w = tid & 63;
        int s0 = (w >> 3) * 2;
        int t0 = (w & 7) * 2;
        const float* q0 = s.qkv + s0 * QLD + head * 64;
        const float* q1 = q0 + QLD;
        const float* k0 = s.qkv + t0 * QLD + 256 + head * 64;
        const float* k1 = k0 + QLD;
        float qk00 = 0.f, qk01 = 0.f, qk10 = 0.f, qk11 = 0.f;
#pragma unroll 4
        for (int d4 = 0; d4 < 16; d4++) {
            float4 a0 = *(const float4*)(q0 + d4 * 4);
            float4 a1 = *(const float4*)(q1 + d4 * 4);
            float4 b0 = *(const float4*)(k0 + d4 * 4);
            float4 b1 = *(const float4*)(k1 + d4 * 4);
            qk00 += a0.x * b0.x + a0.y * b0.y + a0.z * b0.z + a0.w * b0.w;
            qk01 += a0.x * b1.x + a0.y * b1.y + a0.z * b1.z + a0.w * b1.w;
            qk10 += a1.x * b0.x + a1.y * b0.y + a1.z * b0.z + a1.w * b0.w;
            qk11 += a1.x * b1.x + a1.y * b1.y + a1.z * b1.z + a1.w * b1.w;
        }
        float qk[2][2] = {{qk00, qk01}, {qk10, qk11}};
        float logD[2][2], mymax[2];
#pragma unroll
        for (int si = 0; si < 2; si++) {
            int ss = s0 + si;
            mymax[si] = -INFINITY;
#pragma unroll
            for (int tj = 0; tj < 2; tj++) {
                int t_ = t0 + tj;
                float v = (t_ <= ss)
                    ? (s.lf[head * 17 + ss + 1] - s.lf[head * 17 + t_ + 1] + s.igv[t_ * 4 + head])
                    : -INFINITY;
                logD[si][tj] = v;
                mymax[si] = fmaxf(mymax[si], v);
            }
        }
#pragma unroll
        for (int off = 1; off < 8; off <<= 1) {
            mymax[0] = fmaxf(mymax[0], __shfl_xor_sync(0xffffffffu, mymax[0], off));
            mymax[1] = fmaxf(mymax[1], __shfl_xor_sync(0xffffffffu, mymax[1], off));
        }
        float Cc[2][2], rowsum[2] = {0.f, 0.f};
#pragma unroll
        for (int si = 0; si < 2; si++)
#pragma unroll
            for (int tj = 0; tj < 2; tj++) {
                float Dv = expf(logD[si][tj] - mymax[si]);   // exp(-inf)=0 masked
                float Cv = qk[si][tj] * 0.125f * Dv;
                Cc[si][tj] = Cv;
                rowsum[si] += Cv;
            }
#pragma unroll
        for (int off = 1; off < 8; off <<= 1) {
            rowsum[0] += __shfl_xor_sync(0xffffffffu, rowsum[0], off);
            rowsum[1] += __shfl_xor_sync(0xffffffffu, rowsum[1], off);
        }
#pragma unroll
        for (int si = 0; si < 2; si++) {
            float norm = fmaxf(fabsf(rowsum[si]), expf(-mymax[si]));
            float inv = 1.f / (norm + 1e-6f);
#pragma unroll
            for (int tj = 0; tj < 2; tj++)
                s.chat[(head * 16 + s0 + si) * 16 + t0 + tj] = Cc[si][tj] * inv;
        }
    }
    __syncthreads();

    // ---- ht = Chat @ v (register v), LN via warp shuffles, gating, store ----
    {
        float vreg[16];
#pragma unroll
        for (int u = 0; u < 16; u++) vreg[u] = s.qkv[u * QLD + 512 + tid];

        int head = tid >> 6;
        const float* chrow = s.chat + head * 256;
        float acc[16];
#pragma unroll
        for (int t = 0; t < 16; t++) {
            float a = 0.f;
#pragma unroll
            for (int u = 0; u < 16; u++) a += chrow[t * 16 + u] * vreg[u];
            acc[t] = a;
        }
        // per-warp (32-channel) partial sums for LN over 64-channel heads
#pragma unroll
        for (int t = 0; t < 16; t++) {
            float sv = acc[t];
            float qv = acc[t] * acc[t];
#pragma unroll
            for (int off = 16; off >= 1; off >>= 1) {
                sv += __shfl_xor_sync(0xffffffffu, sv, off);
                qv += __shfl_xor_sync(0xffffffffu, qv, off);
            }
            if (lane == 0) {
                s.red[warp * 16 + t]       = sv;
                s.red[128 + warp * 16 + t] = qv;
            }
        }
        __syncthreads();

        int pw = warp ^ 1;
        float skipv = skip[tid];
        float lnv   = lnw[tid];
#pragma unroll
        for (int t = 0; t < 16; t++) {
            float sv = s.red[warp * 16 + t] + s.red[pw * 16 + t];
            float qv = s.red[128 + warp * 16 + t] + s.red[128 + pw * 16 + t];
            float mu = sv * (1.f / 64.f);
            float var = qv * (1.f / 64.f) - mu * mu;
            float rstd = rsqrtf(var + 1e-5f);
            float hn = (acc[t] - mu) * rstd * lnv;
            size_t m = rowbase + ((size_t)t << 10);
            float z = g_up[m * 512 + 256 + tid];
            g_hs[m * 256 + tid] = (hn + skipv * xc[t]) * siluf(z);
        }
    }
}

// =====================================================================
// Kernel 3: down projection, out[b,c,t,h,w] = h_state[m,:] @ W_down
//   128x128 tile (full N), 8x8 micro, transposed A at stride 129
// =====================================================================
__global__ __launch_bounds__(256) void k_down(const float* __restrict__ Wd,
                                              float* __restrict__ out)
{
    extern __shared__ float sm[];
    float* As = sm;              // [64 k][129 m-padded]
    float* Bs = sm + 64 * 129;   // [64 k][128 n]

    const int tid = threadIdx.x;
    const int m0 = blockIdx.x * 128;
    const int mx = tid & 15, ny = tid >> 4;

    float acc[8][8];
#pragma unroll
    for (int i = 0; i < 8; i++)
#pragma unroll
        for (int j = 0; j < 8; j++) acc[i][j] = 0.f;

    for (int kc = 0; kc < 256; kc += 64) {
        {
            // A: float4 along k, scatter-transpose into As[k][m] (stride 129)
            int kx4 = (tid & 15) * 4, mr = tid >> 4;
#pragma unroll
            for (int p = 0; p < 8; p++) {
                int m = mr + p * 16;
                float4 v = *(const float4*)(g_hs + (size_t)(m0 + m) * 256 + kc + kx4);
                As[(kx4 + 0) * 129 + m] = v.x;
                As[(kx4 + 1) * 129 + m] = v.y;
                As[(kx4 + 2) * 129 + m] = v.z;
                As[(kx4 + 3) * 129 + m] = v.w;
            }
            int n4 = (tid & 31) * 4, kr = tid >> 5;
#pragma unroll
            for (int p = 0; p < 8; p++) {
                int k = kr + p * 8;
                *(float4*)(Bs + k * 128 + n4) = *(const float4*)(Wd + (size_t)(kc + k) * 128 + n4);
            }
        }
        __syncthreads();
#pragma unroll 4
        for (int k = 0; k < 64; k++) {
            float av[8];
#pragma unroll
            for (int i = 0; i < 8; i++) av[i] = As[k * 129 + mx + 16 * i];
            float4 b0 = *(const float4*)(Bs + k * 128 + ny * 4);
            float4 b1 = *(const float4*)(Bs + k * 128 + 64 + ny * 4);
            float bv[8] = {b0.x, b0.y, b0.z, b0.w, b1.x, b1.y, b1.z, b1.w};
#pragma unroll
            for (int i = 0; i < 8; i++)
#pragma unroll
                for (int j = 0; j < 8; j++) acc[i][j] += av[i] * bv[j];
        }
        __syncthreads();
    }

    const int hw0 = m0 & 1023;
    const int bt = m0 >> 10;
    float* ob = out + (size_t)(bt >> 4) * 2097152 + (size_t)(bt & 15) * 1024 + hw0;
#pragma unroll
    for (int j = 0; j < 8; j++) {
        int c = ny * 4 + (j & 3) + ((j >> 2) << 6);
#pragma unroll
        for (int i = 0; i < 8; i++)
            ob[(size_t)c * 16384 + mx + 16 * i] = acc[i][j];
    }
}

// =====================================================================
// launch
// =====================================================================
extern "C" void kernel_launch(void* const* d_in, const int* in_sizes, int n_in,
                              void* d_out, int out_size)
{
    const float* x    = (const float*)d_in[0];
    const float* Wup  = (const float*)d_in[1];
    const float* cw   = (const float*)d_in[2];
    const float* cb   = (const float*)d_in[3];
    const float* Wq   = (const float*)d_in[4];
    const float* Wk   = (const float*)d_in[5];
    const float* Wv   = (const float*)d_in[6];
    const float* igw  = (const float*)d_in[7];
    const float* igb  = (const float*)d_in[8];
    const float* fgw  = (const float*)d_in[9];
    const float* fgb  = (const float*)d_in[10];
    const float* lnw  = (const float*)d_in[11];
    const float* skip = (const float*)d_in[12];
    const float* Wd   = (const float*)d_in[13];
    float* out = (float*)d_out;

    (void)in_sizes; (void)n_in; (void)out_size;

    const int smem_up   = (64 * 128 + 64 * 128) * (int)sizeof(float);  // 64 KB
    const int smem_mid  = (int)sizeof(SM2);                            // ~55.3 KB
    const int smem_down = (64 * 129 + 64 * 128) * (int)sizeof(float);  // ~64.3 KB

    cudaFuncSetAttribute(k_up,   cudaFuncAttributeMaxDynamicSharedMemorySize, smem_up);
    cudaFuncSetAttribute(k_mid,  cudaFuncAttributeMaxDynamicSharedMemorySize, smem_mid);
    cudaFuncSetAttribute(k_down, cudaFuncAttributeMaxDynamicSharedMemorySize, smem_down);

    k_up<<<dim3(4, 1024), 256, smem_up>>>(x, Wup);
    k_mid<<<8192, 256, smem_mid>>>(cw, cb, Wq, Wk, Wv, igw, igb, fgw, fgb, lnw, skip);
    k_down<<<1024, 256, smem_down>>>(Wd, out);
}

// round 9
// speedup vs baseline: 1.6543x; 1.0433x over previous
#include <cuda_runtime.h>
#include <math.h>

// ---------------- problem constants ----------------
#define MTOT  131072          // B*T*H*W rows, m = ((b*T+t)*H+h)*W+w
#define QLD   772             // qkv smem row stride (floats): mult of 4 (float4), !=0 mod 32

// ---------------- scratch (device globals; no allocs) ----------------
__device__ float g_up[(size_t)MTOT * 512];   // up-projection output [M,512] (x_m | z)
__device__ float g_hs[(size_t)MTOT * 256];   // h_state [M,256]

__device__ __forceinline__ float siluf(float x) { return x / (1.f + __expf(-x)); }

// ---------------- packed f32x2 helpers (B300 double-rate fp32) ----------------
__device__ __forceinline__ unsigned long long pack2(float lo, float hi) {
    unsigned long long r;
    asm("mov.b64 %0, {%1, %2};" : "=l"(r) : "f"(lo), "f"(hi));
    return r;
}
__device__ __forceinline__ void fma2(unsigned long long& d,
                                     unsigned long long a, unsigned long long b) {
    asm("fma.rn.f32x2 %0, %1, %2, %0;" : "+l"(d) : "l"(a), "l"(b));
}
__device__ __forceinline__ void unpack2(unsigned long long v, float& lo, float& hi) {
    asm("mov.b64 {%0, %1}, %2;" : "=f"(lo), "=f"(hi) : "l"(v));
}

// =====================================================================
// Kernel 1: up projection GEMM  up[m,n] = sum_k xs[m,k] * W_up[k,n]
//   128x128 tile, 8x8 micro (f32x2 packed), kc=64
// =====================================================================
__global__ __launch_bounds__(256) void k_up(const float* __restrict__ x,
                                            const float* __restrict__ Wup)
{
    extern __shared__ float sm[];
    float* As = sm;             // [64 k][128 m]
    float* Bs = sm + 64 * 128;  // [64 k][128 n]

    const int tid = threadIdx.x;
    const int n0 = blockIdx.x * 128;
    const int m0 = blockIdx.y * 128;
    const int hw0 = m0 & 1023;
    const int bt  = m0 >> 10;           // b*16 + t
    const float* xb = x + (size_t)(bt >> 4) * 2097152 + (size_t)(bt & 15) * 1024 + hw0;

    const int mx = tid & 15, ny = tid >> 4;
    const int l4 = (tid & 31) * 4, kr = tid >> 5;  // loader coords

    unsigned long long acc2[4][8];      // [m-pair][n]
#pragma unroll
    for (int i = 0; i < 4; i++)
#pragma unroll
        for (int j = 0; j < 8; j++) acc2[i][j] = 0ULL;

    for (int kc = 0; kc < 128; kc += 64) {
#pragma unroll
        for (int p = 0; p < 8; p++) {
            int k = kr + p * 8;
            *(float4*)(As + k * 128 + l4) = *(const float4*)(xb + (size_t)(kc + k) * 16384 + l4);
            *(float4*)(Bs + k * 128 + l4) = *(const float4*)(Wup + (size_t)(kc + k) * 512 + n0 + l4);
        }
        __syncthreads();
#pragma unroll 4
        for (int k = 0; k < 64; k++) {
            float4 a0 = *(const float4*)(As + k * 128 + mx * 4);
            float4 a1 = *(const float4*)(As + k * 128 + 64 + mx * 4);
            float4 b0 = *(const float4*)(Bs + k * 128 + ny * 4);
            float4 b1 = *(const float4*)(Bs + k * 128 + 64 + ny * 4);
            unsigned long long ap[4];
            ap[0] = pack2(a0.x, a0.y); ap[1] = pack2(a0.z, a0.w);
            ap[2] = pack2(a1.x, a1.y); ap[3] = pack2(a1.z, a1.w);
            unsigned long long bb[8];
            bb[0] = pack2(b0.x, b0.x); bb[1] = pack2(b0.y, b0.y);
            bb[2] = pack2(b0.z, b0.z); bb[3] = pack2(b0.w, b0.w);
            bb[4] = pack2(b1.x, b1.x); bb[5] = pack2(b1.y, b1.y);
            bb[6] = pack2(b1.z, b1.z); bb[7] = pack2(b1.w, b1.w);
#pragma unroll
            for (int i = 0; i < 4; i++)
#pragma unroll
                for (int j = 0; j < 8; j++) fma2(acc2[i][j], ap[i], bb[j]);
        }
        __syncthreads();
    }

    float acc[8][8];
#pragma unroll
    for (int i = 0; i < 4; i++)
#pragma unroll
        for (int j = 0; j < 8; j++) unpack2(acc2[i][j], acc[2 * i][j], acc[2 * i + 1][j]);

#pragma unroll
    for (int i = 0; i < 8; i++) {
        int m = m0 + mx * 4 + (i & 3) + ((i >> 2) << 6);
        float* ob = g_up + (size_t)m * 512 + n0;
        *(float4*)(ob + ny * 4)      = make_float4(acc[i][0], acc[i][1], acc[i][2], acc[i][3]);
        *(float4*)(ob + 64 + ny * 4) = make_float4(acc[i][4], acc[i][5], acc[i][6], acc[i][7]);
    }
}

// =====================================================================
// Kernel 2: fused conv/qkv/gates/mLSTM/LN/gating, one CTA per sequence
//   t-dimension register-resident; q/k/v via intra-warp shuffles
// =====================================================================
struct SM2 {
    float qkv[16 * QLD];        // per t: q[0,256) k[256,512) v[512,768)
    float chat[4 * 16 * 16];
    float lf[4 * 17];
    float igv[64];
    float fgv[64];
    float red[2 * 8 * 16];      // [sum|sq][warp][t]
};

__global__ __launch_bounds__(256) void k_mid(
    const float* __restrict__ cw,  const float* __restrict__ cb,
    const float* __restrict__ Wq,  const float* __restrict__ Wk,
    const float* __restrict__ Wv,
    const float* __restrict__ igw, const float* __restrict__ igb,
    const float* __restrict__ fgw, const float* __restrict__ fgb,
    const float* __restrict__ lnw, const float* __restrict__ skip)
{
    extern __shared__ char smraw[];
    SM2& s = *reinterpret_cast<SM2*>(smraw);
    const int tid  = threadIdx.x;
    const int lane = tid & 31;
    const int warp = tid >> 5;
    const int seq = blockIdx.x;
    const int b = seq >> 10, hw = seq & 1023;
    const size_t rowbase = ((size_t)(b * 16) << 10) + hw;   // + (t<<10) per step

    // ---- A: load x_m, conv+silu, q/k/v via shuffles; all t in registers ----
    float xm[16], xc[16];
#pragma unroll
    for (int t = 0; t < 16; t++)
        xm[t] = g_up[(rowbase + ((size_t)t << 10)) * 512 + tid];

    {
        float c0 = cw[tid], c1 = cw[256 + tid], c2 = cw[512 + tid], c3 = cw[768 + tid];
        float cbv = cb[tid];
#pragma unroll
        for (int t = 0; t < 16; t++) {
            float a = cbv + c3 * xm[t];
            if (t >= 1) a += c2 * xm[t - 1];
            if (t >= 2) a += c1 * xm[t - 2];
            if (t >= 3) a += c0 * xm[t - 3];
            xc[t] = siluf(a);
        }
    }

    {
        float4 wq = *(const float4*)(Wq + 4 * tid);
        float4 wk = *(const float4*)(Wk + 4 * tid);
        float4 wv = *(const float4*)(Wv + 4 * tid);
        int bl = lane & ~3;
#pragma unroll
        for (int t = 0; t < 16; t++) {
            float x0 = __shfl_sync(0xffffffffu, xc[t], bl);
            float x1 = __shfl_sync(0xffffffffu, xc[t], bl + 1);
            float x2 = __shfl_sync(0xffffffffu, xc[t], bl + 2);
            float x3 = __shfl_sync(0xffffffffu, xc[t], bl + 3);
            float m0v = __shfl_sync(0xffffffffu, xm[t], bl);
            float m1v = __shfl_sync(0xffffffffu, xm[t], bl + 1);
            float m2v = __shfl_sync(0xffffffffu, xm[t], bl + 2);
            float m3v = __shfl_sync(0xffffffffu, xm[t], bl + 3);
            float q = wq.x * x0 + wq.y * x1 + wq.z * x2 + wq.w * x3;
            float k = wk.x * x0 + wk.y * x1 + wk.z * x2 + wk.w * x3;
            float v = wv.x * m0v + wv.y * m1v + wv.z * m2v + wv.w * m3v;
            s.qkv[t * QLD + tid]       = q;
            s.qkv[t * QLD + 256 + tid] = k;
            s.qkv[t * QLD + 512 + tid] = v;
        }
    }
    __syncthreads();

    // ---- gates: ig/fg [t,h] over 768 inputs; 16 lanes split-K + shfl reduce ----
    {
        int t = tid >> 4, p = tid & 15;
        const float* row = s.qkv + t * QLD;
        float ai[4] = {0.f, 0.f, 0.f, 0.f}, af[4] = {0.f, 0.f, 0.f, 0.f};
#pragma unroll
        for (int ii = 0; ii < 12; ii++) {
            int idx = p * 4 + ii * 64;
            float4 xv = *(const float4*)(row + idx);
            float vals[4] = {xv.x, xv.y, xv.z, xv.w};
#pragma unroll
            for (int e = 0; e < 4; e++) {
                float val = vals[e];
                float4 wi = *(const float4*)(igw + (idx + e) * 4);
                float4 wf = *(const float4*)(fgw + (idx + e) * 4);
                ai[0] += val * wi.x; ai[1] += val * wi.y; ai[2] += val * wi.z; ai[3] += val * wi.w;
                af[0] += val * wf.x; af[1] += val * wf.y; af[2] += val * wf.z; af[3] += val * wf.w;
            }
        }
#pragma unroll
        for (int off = 1; off < 16; off <<= 1) {
#pragma unroll
            for (int h = 0; h < 4; h++) {
                ai[h] += __shfl_xor_sync(0xffffffffu, ai[h], off);
                af[h] += __shfl_xor_sync(0xffffffffu, af[h], off);
            }
        }
        if (p == 0) {
#pragma unroll
            for (int h = 0; h < 4; h++) {
                s.igv[t * 4 + h] = ai[h] + igb[h];
                s.fgv[t * 4 + h] = af[h] + fgb[h];
            }
        }
    }
    __syncthreads();

    // ---- cumulative log-sigmoid of forget gates (4 threads) ----
    if (tid < 4) {
        int h = tid;
        float run = 0.f;
        s.lf[h * 17 + 0] = 0.f;
#pragma unroll
        for (int t = 0; t < 16; t++) {
            float xg = s.fgv[t * 4 + h];
            float ls = fminf(xg, 0.f) - log1pf(__expf(-fabsf(xg)));
            run += ls;
            s.lf[h * 17 + t + 1] = run;
        }
    }
    __syncthreads();

    // ---- qk + gate matrix + normalizer -> chat (per head: 64 thr, 2x2 tiles) ----
    {
        int head = tid >> 6, w = tid & 63;
        int s0 = (w >> 3) * 2;
        int t0 = (w & 7) * 2;
        const float* q0 = s.qkv + s0 * QLD + head * 64;
        const float* q1 = q0 + QLD;
        const float* k0 = s.qkv + t0 * QLD + 256 + head * 64;
        const float* k1 = k0 + QLD;
        float qk00 = 0.f, qk01 = 0.f, qk10 = 0.f, qk11 = 0.f;
#pragma unroll 4
        for (int d4 = 0; d4 < 16; d4++) {
            float4 a0 = *(const float4*)(q0 + d4 * 4);
            float4 a1 = *(const float4*)(q1 + d4 * 4);
            float4 b0 = *(const float4*)(k0 + d4 * 4);
            float4 b1 = *(const float4*)(k1 + d4 * 4);
            qk00 += a0.x * b0.x + a0.y * b0.y + a0.z * b0.z + a0.w * b0.w;
            qk01 += a0.x * b1.x + a0.y * b1.y + a0.z * b1.z + a0.w * b1.w;
            qk10 += a1.x * b0.x + a1.y * b0.y + a1.z * b0.z + a1.w * b0.w;
            qk11 += a1.x * b1.x + a1.y * b1.y + a1.z * b1.z + a1.w * b1.w;
        }
        float qk[2][2] = {{qk00, qk01}, {qk10, qk11}};
        float logD[2][2], mymax[2];
#pragma unroll
        for (int si = 0; si < 2; si++) {
            int ss = s0 + si;
            mymax[si] = -INFINITY;
#pragma unroll
            for (int tj = 0; tj < 2; tj++) {
                int t_ = t0 + tj;
                float v = (t_ <= ss)
                    ? (s.lf[head * 17 + ss + 1] - s.lf[head * 17 + t_ + 1] + s.igv[t_ * 4 + head])
                    : -INFINITY;
                logD[si][tj] = v;
                mymax[si] = fmaxf(mymax[si], v);
            }
        }
#pragma unroll
        for (int off = 1; off < 8; off <<= 1) {
            mymax[0] = fmaxf(mymax[0], __shfl_xor_sync(0xffffffffu, mymax[0], off));
            mymax[1] = fmaxf(mymax[1], __shfl_xor_sync(0xffffffffu, mymax[1], off));
        }
        float Cc[2][2], rowsum[2] = {0.f, 0.f};
#pragma unroll
        for (int si = 0; si < 2; si++)
#pragma unroll
            for (int tj = 0; tj < 2; tj++) {
                float Dv = expf(logD[si][tj] - mymax[si]);   // exp(-inf)=0 masked
                float Cv = qk[si][tj] * 0.125f * Dv;
                Cc[si][tj] = Cv;
                rowsum[si] += Cv;
            }
#pragma unroll
        for (int off = 1; off < 8; off <<= 1) {
            rowsum[0] += __shfl_xor_sync(0xffffffffu, rowsum[0], off);
            rowsum[1] += __shfl_xor_sync(0xffffffffu, rowsum[1], off);
        }
#pragma unroll
        for (int si = 0; si < 2; si++) {
            float norm = fmaxf(fabsf(rowsum[si]), expf(-mymax[si]));
            float inv = 1.f / (norm + 1e-6f);
#pragma unroll
            for (int tj = 0; tj < 2; tj++)
                s.chat[(head * 16 + s0 + si) * 16 + t0 + tj] = Cc[si][tj] * inv;
        }
    }
    __syncthreads();

    // ---- ht = Chat @ v (register v, f32x2 packed), LN, gating, store ----
    {
        float vreg[16];
#pragma unroll
        for (int u = 0; u < 16; u++) vreg[u] = s.qkv[u * QLD + 512 + tid];
        unsigned long long vp[8];
#pragma unroll
        for (int i = 0; i < 8; i++) vp[i] = pack2(vreg[2 * i], vreg[2 * i + 1]);

        int head = tid >> 6;
        const float* chrow = s.chat + head * 256;
        float acc[16];
#pragma unroll
        for (int t = 0; t < 16; t++) {
            unsigned long long a2 = 0ULL;
#pragma unroll
            for (int u4 = 0; u4 < 4; u4++) {
                float4 c = *(const float4*)(chrow + t * 16 + u4 * 4);
                fma2(a2, pack2(c.x, c.y), vp[u4 * 2]);
                fma2(a2, pack2(c.z, c.w), vp[u4 * 2 + 1]);
            }
            float lo, hi;
            unpack2(a2, lo, hi);
            acc[t] = lo + hi;
        }
        // per-warp (32-channel) partial sums for LN over 64-channel heads
#pragma unroll
        for (int t = 0; t < 16; t++) {
            float sv = acc[t];
            float qv = acc[t] * acc[t];
#pragma unroll
            for (int off = 16; off >= 1; off >>= 1) {
                sv += __shfl_xor_sync(0xffffffffu, sv, off);
                qv += __shfl_xor_sync(0xffffffffu, qv, off);
            }
            if (lane == 0) {
                s.red[warp * 16 + t]       = sv;
                s.red[128 + warp * 16 + t] = qv;
            }
        }
        __syncthreads();

        int pw = warp ^ 1;
        float skipv = skip[tid];
        float lnv   = lnw[tid];
#pragma unroll
        for (int t = 0; t < 16; t++) {
            float sv = s.red[warp * 16 + t] + s.red[pw * 16 + t];
            float qv = s.red[128 + warp * 16 + t] + s.red[128 + pw * 16 + t];
            float mu = sv * (1.f / 64.f);
            float var = qv * (1.f / 64.f) - mu * mu;
            float rstd = rsqrtf(var + 1e-5f);
            float hn = (acc[t] - mu) * rstd * lnv;
            size_t m = rowbase + ((size_t)t << 10);
            float z = g_up[m * 512 + 256 + tid];
            g_hs[m * 256 + tid] = (hn + skipv * xc[t]) * siluf(z);
        }
    }
}

// =====================================================================
// Kernel 3: down projection, out[b,c,t,h,w] = h_state[m,:] @ W_down
//   128x128 tile (full N), 8x8 micro (f32x2 packed), transposed A at 129
// =====================================================================
__global__ __launch_bounds__(256) void k_down(const float* __restrict__ Wd,
                                              float* __restrict__ out)
{
    extern __shared__ float sm[];
    float* As = sm;              // [64 k][129 m-padded]
    float* Bs = sm + 64 * 129;   // [64 k][128 n]

    const int tid = threadIdx.x;
    const int m0 = blockIdx.x * 128;
    const int mx = tid & 15, ny = tid >> 4;

    unsigned long long acc2[4][8];
#pragma unroll
    for (int i = 0; i < 4; i++)
#pragma unroll
        for (int j = 0; j < 8; j++) acc2[i][j] = 0ULL;

    for (int kc = 0; kc < 256; kc += 64) {
        {
            // A: float4 along k, scatter-transpose into As[k][m] (stride 129)
            int kx4 = (tid & 15) * 4, mr = tid >> 4;
#pragma unroll
            for (int p = 0; p < 8; p++) {
                int m = mr + p * 16;
                float4 v = *(const float4*)(g_hs + (size_t)(m0 + m) * 256 + kc + kx4);
                As[(kx4 + 0) * 129 + m] = v.x;
                As[(kx4 + 1) * 129 + m] = v.y;
                As[(kx4 + 2) * 129 + m] = v.z;
                As[(kx4 + 3) * 129 + m] = v.w;
            }
            int n4 = (tid & 31) * 4, kr = tid >> 5;
#pragma unroll
            for (int p = 0; p < 8; p++) {
                int k = kr + p * 8;
                *(float4*)(Bs + k * 128 + n4) = *(const float4*)(Wd + (size_t)(kc + k) * 128 + n4);
            }
        }
        __syncthreads();
#pragma unroll 4
        for (int k = 0; k < 64; k++) {
            float av[8];
#pragma unroll
            for (int i = 0; i < 8; i++) av[i] = As[k * 129 + mx + 16 * i];
            float4 b0 = *(const float4*)(Bs + k * 128 + ny * 4);
            float4 b1 = *(const float4*)(Bs + k * 128 + 64 + ny * 4);
            unsigned long long ap[4];
            ap[0] = pack2(av[0], av[1]); ap[1] = pack2(av[2], av[3]);
            ap[2] = pack2(av[4], av[5]); ap[3] = pack2(av[6], av[7]);
            unsigned long long bb[8];
            bb[0] = pack2(b0.x, b0.x); bb[1] = pack2(b0.y, b0.y);
            bb[2] = pack2(b0.z, b0.z); bb[3] = pack2(b0.w, b0.w);
            bb[4] = pack2(b1.x, b1.x); bb[5] = pack2(b1.y, b1.y);
            bb[6] = pack2(b1.z, b1.z); bb[7] = pack2(b1.w, b1.w);
#pragma unroll
            for (int i = 0; i < 4; i++)
#pragma unroll
                for (int j = 0; j < 8; j++) fma2(acc2[i][j], ap[i], bb[j]);
        }
        __syncthreads();
    }

    float acc[8][8];
#pragma unroll
    for (int i = 0; i < 4; i++)
#pragma unroll
        for (int j = 0; j < 8; j++) unpack2(acc2[i][j], acc[2 * i][j], acc[2 * i + 1][j]);

    const int hw0 = m0 & 1023;
    const int bt = m0 >> 10;
    float* ob = out + (size_t)(bt >> 4) * 2097152 + (size_t)(bt & 15) * 1024 + hw0;
#pragma unroll
    for (int j = 0; j < 8; j++) {
        int c = ny * 4 + (j & 3) + ((j >> 2) << 6);
#pragma unroll
        for (int i = 0; i < 8; i++)
            ob[(size_t)c * 16384 + mx + 16 * i] = acc[i][j];
    }
}

// =====================================================================
// launch
// =====================================================================
extern "C" void kernel_launch(void* const* d_in, const int* in_sizes, int n_in,
                              void* d_out, int out_size)
{
    const float* x    = (const float*)d_in[0];
    const float* Wup  = (const float*)d_in[1];
    const float* cw   = (const float*)d_in[2];
    const float* cb   = (const float*)d_in[3];
    const float* Wq   = (const float*)d_in[4];
    const float* Wk   = (const float*)d_in[5];
    const float* Wv   = (const float*)d_in[6];
    const float* igw  = (const float*)d_in[7];
    const float* igb  = (const float*)d_in[8];
    const float* fgw  = (const float*)d_in[9];
    const float* fgb  = (const float*)d_in[10];
    const float* lnw  = (const float*)d_in[11];
    const float* skip = (const float*)d_in[12];
    const float* Wd   = (const float*)d_in[13];
    float* out = (float*)d_out;

    (void)in_sizes; (void)n_in; (void)out_size;

    const int smem_up   = (64 * 128 + 64 * 128) * (int)sizeof(float);  // 64 KB
    const int smem_mid  = (int)sizeof(SM2);                            // ~55.3 KB
    const int smem_down = (64 * 129 + 64 * 128) * (int)sizeof(float);  // ~64.3 KB

    cudaFuncSetAttribute(k_up,   cudaFuncAttributeMaxDynamicSharedMemorySize, smem_up);
    cudaFuncSetAttribute(k_mid,  cudaFuncAttributeMaxDynamicSharedMemorySize, smem_mid);
    cudaFuncSetAttribute(k_down, cudaFuncAttributeMaxDynamicSharedMemorySize, smem_down);

    k_up<<<dim3(4, 1024), 256, smem_up>>>(x, Wup);
    k_mid<<<8192, 256, smem_mid>>>(cw, cb, Wq, Wk, Wv, igw, igb, fgw, fgb, lnw, skip);
    k_down<<<1024, 256, smem_down>>>(Wd, out);
}

// round 12
// speedup vs baseline: 1.7291x; 1.0452x over previous
#include <cuda_runtime.h>
#include <math.h>

// ---------------- problem constants ----------------
#define MTOT  131072          // B*T*H*W rows, m = ((b*T+t)*H+h)*W+w
#define QLD   772             // qkv smem row stride (floats): mult of 4 (float4), !=0 mod 32

// ---------------- scratch (device globals; no allocs) ----------------
__device__ float g_up[(size_t)MTOT * 512];   // up-projection output [M,512] (x_m | z)
__device__ float g_hs[(size_t)MTOT * 256];   // h_state [M,256]

__device__ __forceinline__ float siluf(float x) { return x / (1.f + __expf(-x)); }

// ---------------- packed f32x2 helpers (B300 double-rate fp32) ----------------
__device__ __forceinline__ unsigned long long pack2(float lo, float hi) {
    unsigned long long r;
    asm("mov.b64 %0, {%1, %2};" : "=l"(r) : "f"(lo), "f"(hi));
    return r;
}
__device__ __forceinline__ void fma2(unsigned long long& d,
                                     unsigned long long a, unsigned long long b) {
    asm("fma.rn.f32x2 %0, %1, %2, %0;" : "+l"(d) : "l"(a), "l"(b));
}
__device__ __forceinline__ void unpack2(unsigned long long v, float& lo, float& hi) {
    asm("mov.b64 {%0, %1}, %2;" : "=f"(lo), "=f"(hi) : "l"(v));
}

// =====================================================================
// Kernel 1: up projection GEMM  up[m,n] = sum_k xs[m,k] * W_up[k,n]
//   128x128 tile, 8x8 micro (f32x2 packed), kc=64
// =====================================================================
__global__ __launch_bounds__(256) void k_up(const float* __restrict__ x,
                                            const float* __restrict__ Wup)
{
    extern __shared__ float sm[];
    float* As = sm;             // [64 k][128 m]
    float* Bs = sm + 64 * 128;  // [64 k][128 n]

    const int tid = threadIdx.x;
    const int n0 = blockIdx.x * 128;
    const int m0 = blockIdx.y * 128;
    const int hw0 = m0 & 1023;
    const int bt  = m0 >> 10;           // b*16 + t
    const float* xb = x + (size_t)(bt >> 4) * 2097152 + (size_t)(bt & 15) * 1024 + hw0;

    const int mx = tid & 15, ny = tid >> 4;
    const int l4 = (tid & 31) * 4, kr = tid >> 5;  // loader coords

    unsigned long long acc2[4][8];      // [m-pair][n]
#pragma unroll
    for (int i = 0; i < 4; i++)
#pragma unroll
        for (int j = 0; j < 8; j++) acc2[i][j] = 0ULL;

    for (int kc = 0; kc < 128; kc += 64) {
#pragma unroll
        for (int p = 0; p < 8; p++) {
            int k = kr + p * 8;
            *(float4*)(As + k * 128 + l4) = *(const float4*)(xb + (size_t)(kc + k) * 16384 + l4);
            *(float4*)(Bs + k * 128 + l4) = *(const float4*)(Wup + (size_t)(kc + k) * 512 + n0 + l4);
        }
        __syncthreads();
#pragma unroll 4
        for (int k = 0; k < 64; k++) {
            float4 a0 = *(const float4*)(As + k * 128 + mx * 4);
            float4 a1 = *(const float4*)(As + k * 128 + 64 + mx * 4);
            float4 b0 = *(const float4*)(Bs + k * 128 + ny * 4);
            float4 b1 = *(const float4*)(Bs + k * 128 + 64 + ny * 4);
            unsigned long long ap[4];
            ap[0] = pack2(a0.x, a0.y); ap[1] = pack2(a0.z, a0.w);
            ap[2] = pack2(a1.x, a1.y); ap[3] = pack2(a1.z, a1.w);
            unsigned long long bb[8];
            bb[0] = pack2(b0.x, b0.x); bb[1] = pack2(b0.y, b0.y);
            bb[2] = pack2(b0.z, b0.z); bb[3] = pack2(b0.w, b0.w);
            bb[4] = pack2(b1.x, b1.x); bb[5] = pack2(b1.y, b1.y);
            bb[6] = pack2(b1.z, b1.z); bb[7] = pack2(b1.w, b1.w);
#pragma unroll
            for (int i = 0; i < 4; i++)
#pragma unroll
                for (int j = 0; j < 8; j++) fma2(acc2[i][j], ap[i], bb[j]);
        }
        __syncthreads();
    }

    float acc[8][8];
#pragma unroll
    for (int i = 0; i < 4; i++)
#pragma unroll
        for (int j = 0; j < 8; j++) unpack2(acc2[i][j], acc[2 * i][j], acc[2 * i + 1][j]);

#pragma unroll
    for (int i = 0; i < 8; i++) {
        int m = m0 + mx * 4 + (i & 3) + ((i >> 2) << 6);
        float* ob = g_up + (size_t)m * 512 + n0;
        *(float4*)(ob + ny * 4)      = make_float4(acc[i][0], acc[i][1], acc[i][2], acc[i][3]);
        *(float4*)(ob + 64 + ny * 4) = make_float4(acc[i][4], acc[i][5], acc[i][6], acc[i][7]);
    }
}

// =====================================================================
// Kernel 2: fused conv/qkv/gates/mLSTM/LN/gating, one CTA per sequence
//   t-dimension register-resident; q/k/v via intra-warp shuffles
// =====================================================================
struct SM2 {
    float qkv[16 * QLD];        // per t: q[0,256) k[256,512) v[512,768)
    float chat[4 * 16 * 16];
    float lf[4 * 17];
    float igv[64];
    float fgv[64];
    float red[2 * 8 * 16];      // [sum|sq][warp][t]
};

__global__ __launch_bounds__(256, 3) void k_mid(
    const float* __restrict__ cw,  const float* __restrict__ cb,
    const float* __restrict__ Wq,  const float* __restrict__ Wk,
    const float* __restrict__ Wv,
    const float* __restrict__ igw, const float* __restrict__ igb,
    const float* __restrict__ fgw, const float* __restrict__ fgb,
    const float* __restrict__ lnw, const float* __restrict__ skip)
{
    extern __shared__ char smraw[];
    SM2& s = *reinterpret_cast<SM2*>(smraw);
    const int tid  = threadIdx.x;
    const int lane = tid & 31;
    const int warp = tid >> 5;
    const int seq = blockIdx.x;
    const int b = seq >> 10, hw = seq & 1023;
    const size_t rowbase = ((size_t)(b * 16) << 10) + hw;   // + (t<<10) per step

    // ---- A: load x_m, conv+silu, q/k/v via shuffles; all t in registers ----
    float xm[16], xc[16];
#pragma unroll
    for (int t = 0; t < 16; t++)
        xm[t] = g_up[(rowbase + ((size_t)t << 10)) * 512 + tid];

    {
        float c0 = cw[tid], c1 = cw[256 + tid], c2 = cw[512 + tid], c3 = cw[768 + tid];
        float cbv = cb[tid];
#pragma unroll
        for (int t = 0; t < 16; t++) {
            float a = cbv + c3 * xm[t];
            if (t >= 1) a += c2 * xm[t - 1];
            if (t >= 2) a += c1 * xm[t - 2];
            if (t >= 3) a += c0 * xm[t - 3];
            xc[t] = siluf(a);
        }
    }

    {
        float4 wq = *(const float4*)(Wq + 4 * tid);
        float4 wk = *(const float4*)(Wk + 4 * tid);
        float4 wv = *(const float4*)(Wv + 4 * tid);
        int bl = lane & ~3;
#pragma unroll
        for (int t = 0; t < 16; t++) {
            float x0 = __shfl_sync(0xffffffffu, xc[t], bl);
            float x1 = __shfl_sync(0xffffffffu, xc[t], bl + 1);
            float x2 = __shfl_sync(0xffffffffu, xc[t], bl + 2);
            float x3 = __shfl_sync(0xffffffffu, xc[t], bl + 3);
            float m0v = __shfl_sync(0xffffffffu, xm[t], bl);
            float m1v = __shfl_sync(0xffffffffu, xm[t], bl + 1);
            float m2v = __shfl_sync(0xffffffffu, xm[t], bl + 2);
            float m3v = __shfl_sync(0xffffffffu, xm[t], bl + 3);
            float q = wq.x * x0 + wq.y * x1 + wq.z * x2 + wq.w * x3;
            float k = wk.x * x0 + wk.y * x1 + wk.z * x2 + wk.w * x3;
            float v = wv.x * m0v + wv.y * m1v + wv.z * m2v + wv.w * m3v;
            s.qkv[t * QLD + tid]       = q;
            s.qkv[t * QLD + 256 + tid] = k;
            s.qkv[t * QLD + 512 + tid] = v;
        }
    }
    __syncthreads();

    // ---- gates: ig/fg [t,h] over 768 inputs; 16 lanes split-K + shfl reduce ----
    {
        int t = tid >> 4, p = tid & 15;
        const float* row = s.qkv + t * QLD;
        float ai[4] = {0.f, 0.f, 0.f, 0.f}, af[4] = {0.f, 0.f, 0.f, 0.f};
#pragma unroll
        for (int ii = 0; ii < 12; ii++) {
            int idx = p * 4 + ii * 64;
            float4 xv = *(const float4*)(row + idx);
            float vals[4] = {xv.x, xv.y, xv.z, xv.w};
#pragma unroll
            for (int e = 0; e < 4; e++) {
                float val = vals[e];
                float4 wi = *(const float4*)(igw + (idx + e) * 4);
                float4 wf = *(const float4*)(fgw + (idx + e) * 4);
                ai[0] += val * wi.x; ai[1] += val * wi.y; ai[2] += val * wi.z; ai[3] += val * wi.w;
                af[0] += val * wf.x; af[1] += val * wf.y; af[2] += val * wf.z; af[3] += val * wf.w;
            }
        }
#pragma unroll
        for (int off = 1; off < 16; off <<= 1) {
#pragma unroll
            for (int h = 0; h < 4; h++) {
                ai[h] += __shfl_xor_sync(0xffffffffu, ai[h], off);
                af[h] += __shfl_xor_sync(0xffffffffu, af[h], off);
            }
        }
        if (p == 0) {
#pragma unroll
            for (int h = 0; h < 4; h++) {
                s.igv[t * 4 + h] = ai[h] + igb[h];
                s.fgv[t * 4 + h] = af[h] + fgb[h];
            }
        }
    }
    __syncthreads();

    // ---- log-sigmoid of forget gates: parallel over 64 (t,h), then prefix ----
    if (tid < 64) {
        int t = tid >> 2, h = tid & 3;
        float xg = s.fgv[t * 4 + h];
        s.lf[h * 17 + t + 1] = fminf(xg, 0.f) - __logf(1.f + __expf(-fabsf(xg)));
    }
    __syncthreads();
    if (tid < 4) {
        int h = tid;
        float run = 0.f;
        s.lf[h * 17 + 0] = 0.f;
#pragma unroll
        for (int t = 0; t < 16; t++) {
            run += s.lf[h * 17 + t + 1];
            s.lf[h * 17 + t + 1] = run;
        }
    }
    __syncthreads();

    // ---- qk + gate matrix + normalizer -> chat (per head: 64 thr, 2x2 tiles) ----
    {
        int head = tid >> 6, w = tid & 63;
        int s0 = (w >> 3) * 2;
        int t0 = (w & 7) * 2;
        const float* q0 = s.qkv + s0 * QLD + head * 64;
        const float* q1 = q0 + QLD;
        const float* k0 = s.qkv + t0 * QLD + 256 + head * 64;
        const float* k1 = k0 + QLD;
        float qk00 = 0.f, qk01 = 0.f, qk10 = 0.f, qk11 = 0.f;
#pragma unroll 4
        for (int d4 = 0; d4 < 16; d4++) {
            float4 a0 = *(const float4*)(q0 + d4 * 4);
            float4 a1 = *(const float4*)(q1 + d4 * 4);
            float4 b0 = *(const float4*)(k0 + d4 * 4);
            float4 b1 = *(const float4*)(k1 + d4 * 4);
            qk00 += a0.x * b0.x + a0.y * b0.y + a0.z * b0.z + a0.w * b0.w;
            qk01 += a0.x * b1.x + a0.y * b1.y + a0.z * b1.z + a0.w * b1.w;
            qk10 += a1.x * b0.x + a1.y * b0.y + a1.z * b0.z + a1.w * b0.w;
            qk11 += a1.x * b1.x + a1.y * b1.y + a1.z * b1.z + a1.w * b1.w;
        }
        float qk[2][2] = {{qk00, qk01}, {qk10, qk11}};
        float logD[2][2], mymax[2];
#pragma unroll
        for (int si = 0; si < 2; si++) {
            int ss = s0 + si;
            mymax[si] = -INFINITY;
#pragma unroll
            for (int tj = 0; tj < 2; tj++) {
                int t_ = t0 + tj;
                float v = (t_ <= ss)
                    ? (s.lf[head * 17 + ss + 1] - s.lf[head * 17 + t_ + 1] + s.igv[t_ * 4 + head])
                    : -INFINITY;
                logD[si][tj] = v;
                mymax[si] = fmaxf(mymax[si], v);
            }
        }
#pragma unroll
        for (int off = 1; off < 8; off <<= 1) {
            mymax[0] = fmaxf(mymax[0], __shfl_xor_sync(0xffffffffu, mymax[0], off));
            mymax[1] = fmaxf(mymax[1], __shfl_xor_sync(0xffffffffu, mymax[1], off));
        }
        float Cc[2][2], rowsum[2] = {0.f, 0.f};
#pragma unroll
        for (int si = 0; si < 2; si++)
#pragma unroll
            for (int tj = 0; tj < 2; tj++) {
                float Dv = __expf(logD[si][tj] - mymax[si]);   // __expf(-inf)=0 masked
                float Cv = qk[si][tj] * 0.125f * Dv;
                Cc[si][tj] = Cv;
                rowsum[si] += Cv;
            }
#pragma unroll
        for (int off = 1; off < 8; off <<= 1) {
            rowsum[0] += __shfl_xor_sync(0xffffffffu, rowsum[0], off);
            rowsum[1] += __shfl_xor_sync(0xffffffffu, rowsum[1], off);
        }
#pragma unroll
        for (int si = 0; si < 2; si++) {
            float norm = fmaxf(fabsf(rowsum[si]), __expf(-mymax[si]));
            float inv = __fdividef(1.f, norm + 1e-6f);
#pragma unroll
            for (int tj = 0; tj < 2; tj++)
                s.chat[(head * 16 + s0 + si) * 16 + t0 + tj] = Cc[si][tj] * inv;
        }
    }
    __syncthreads();

    // ---- ht = Chat @ v (register v, f32x2 packed), LN, gating, store ----
    {
        float vreg[16];
#pragma unroll
        for (int u = 0; u < 16; u++) vreg[u] = s.qkv[u * QLD + 512 + tid];
        unsigned long long vp[8];
#pragma unroll
        for (int i = 0; i < 8; i++) vp[i] = pack2(vreg[2 * i], vreg[2 * i + 1]);

        int head = tid >> 6;
        const float* chrow = s.chat + head * 256;
        float acc[16];
#pragma unroll
        for (int t = 0; t < 16; t++) {
            unsigned long long a2 = 0ULL;
#pragma unroll
            for (int u4 = 0; u4 < 4; u4++) {
                float4 c = *(const float4*)(chrow + t * 16 + u4 * 4);
                fma2(a2, pack2(c.x, c.y), vp[u4 * 2]);
                fma2(a2, pack2(c.z, c.w), vp[u4 * 2 + 1]);
            }
            float lo, hi;
            unpack2(a2, lo, hi);
            acc[t] = lo + hi;
        }
        // per-warp (32-channel) partial sums for LN over 64-channel heads
#pragma unroll
        for (int t = 0; t < 16; t++) {
            float sv = acc[t];
            float qv = acc[t] * acc[t];
#pragma unroll
            for (int off = 16; off >= 1; off >>= 1) {
                sv += __shfl_xor_sync(0xffffffffu, sv, off);
                qv += __shfl_xor_sync(0xffffffffu, qv, off);
            }
            if (lane == 0) {
                s.red[warp * 16 + t]       = sv;
                s.red[128 + warp * 16 + t] = qv;
            }
        }
        __syncthreads();

        int pw = warp ^ 1;
        float skipv = skip[tid];
        float lnv   = lnw[tid];
#pragma unroll
        for (int t = 0; t < 16; t++) {
            float sv = s.red[warp * 16 + t] + s.red[pw * 16 + t];
            float qv = s.red[128 + warp * 16 + t] + s.red[128 + pw * 16 + t];
            float mu = sv * (1.f / 64.f);
            float var = qv * (1.f / 64.f) - mu * mu;
            float rstd = rsqrtf(var + 1e-5f);
            float hn = (acc[t] - mu) * rstd * lnv;
            size_t m = rowbase + ((size_t)t << 10);
            float z = g_up[m * 512 + 256 + tid];
            g_hs[m * 256 + tid] = (hn + skipv * xc[t]) * siluf(z);
        }
    }
}

// =====================================================================
// Kernel 3: down projection, out[b,c,t,h,w] = h_state[m,:] @ W_down
//   128x128 tile (full N), 8x8 micro (f32x2 packed), transposed A at 129
// =====================================================================
__global__ __launch_bounds__(256) void k_down(const float* __restrict__ Wd,
                                              float* __restrict__ out)
{
    extern __shared__ float sm[];
    float* As = sm;              // [64 k][129 m-padded]
    float* Bs = sm + 64 * 129;   // [64 k][128 n]

    const int tid = threadIdx.x;
    const int m0 = blockIdx.x * 128;
    const int mx = tid & 15, ny = tid >> 4;

    unsigned long long acc2[4][8];
#pragma unroll
    for (int i = 0; i < 4; i++)
#pragma unroll
        for (int j = 0; j < 8; j++) acc2[i][j] = 0ULL;

    for (int kc = 0; kc < 256; kc += 64) {
        {
            // A: float4 along k, scatter-transpose into As[k][m] (stride 129)
            int kx4 = (tid & 15) * 4, mr = tid >> 4;
#pragma unroll
            for (int p = 0; p < 8; p++) {
                int m = mr + p * 16;
                float4 v = *(const float4*)(g_hs + (size_t)(m0 + m) * 256 + kc + kx4);
                As[(kx4 + 0) * 129 + m] = v.x;
                As[(kx4 + 1) * 129 + m] = v.y;
                As[(kx4 + 2) * 129 + m] = v.z;
                As[(kx4 + 3) * 129 + m] = v.w;
            }
            int n4 = (tid & 31) * 4, kr = tid >> 5;
#pragma unroll
            for (int p = 0; p < 8; p++) {
                int k = kr + p * 8;
                *(float4*)(Bs + k * 128 + n4) = *(const float4*)(Wd + (size_t)(kc + k) * 128 + n4);
            }
        }
        __syncthreads();
#pragma unroll 4
        for (int k = 0; k < 64; k++) {
            float av[8];
#pragma unroll
            for (int i = 0; i < 8; i++) av[i] = As[k * 129 + mx + 16 * i];
            float4 b0 = *(const float4*)(Bs + k * 128 + ny * 4);
            float4 b1 = *(const float4*)(Bs + k * 128 + 64 + ny * 4);
            unsigned long long ap[4];
            ap[0] = pack2(av[0], av[1]); ap[1] = pack2(av[2], av[3]);
            ap[2] = pack2(av[4], av[5]); ap[3] = pack2(av[6], av[7]);
            unsigned long long bb[8];
            bb[0] = pack2(b0.x, b0.x); bb[1] = pack2(b0.y, b0.y);
            bb[2] = pack2(b0.z, b0.z); bb[3] = pack2(b0.w, b0.w);
            bb[4] = pack2(b1.x, b1.x); bb[5] = pack2(b1.y, b1.y);
            bb[6] = pack2(b1.z, b1.z); bb[7] = pack2(b1.w, b1.w);
#pragma unroll
            for (int i = 0; i < 4; i++)
#pragma unroll
                for (int j = 0; j < 8; j++) fma2(acc2[i][j], ap[i], bb[j]);
        }
        __syncthreads();
    }

    float acc[8][8];
#pragma unroll
    for (int i = 0; i < 4; i++)
#pragma unroll
        for (int j = 0; j < 8; j++) unpack2(acc2[i][j], acc[2 * i][j], acc[2 * i + 1][j]);

    const int hw0 = m0 & 1023;
    const int bt = m0 >> 10;
    float* ob = out + (size_t)(bt >> 4) * 2097152 + (size_t)(bt & 15) * 1024 + hw0;
#pragma unroll
    for (int j = 0; j < 8; j++) {
        int c = ny * 4 + (j & 3) + ((j >> 2) << 6);
#pragma unroll
        for (int i = 0; i < 8; i++)
            ob[(size_t)c * 16384 + mx + 16 * i] = acc[i][j];
    }
}

// =====================================================================
// launch
// =====================================================================
extern "C" void kernel_launch(void* const* d_in, const int* in_sizes, int n_in,
                              void* d_out, int out_size)
{
    const float* x    = (const float*)d_in[0];
    const float* Wup  = (const float*)d_in[1];
    const float* cw   = (const float*)d_in[2];
    const float* cb   = (const float*)d_in[3];
    const float* Wq   = (const float*)d_in[4];
    const float* Wk   = (const float*)d_in[5];
    const float* Wv   = (const float*)d_in[6];
    const float* igw  = (const float*)d_in[7];
    const float* igb  = (const float*)d_in[8];
    const float* fgw  = (const float*)d_in[9];
    const float* fgb  = (const float*)d_in[10];
    const float* lnw  = (const float*)d_in[11];
    const float* skip = (const float*)d_in[12];
    const float* Wd   = (const float*)d_in[13];
    float* out = (float*)d_out;

    (void)in_sizes; (void)n_in; (void)out_size;

    const int smem_up   = (64 * 128 + 64 * 128) * (int)sizeof(float);  // 64 KB
    const int smem_mid  = (int)sizeof(SM2);                            // ~55.3 KB
    const int smem_down = (64 * 129 + 64 * 128) * (int)sizeof(float);  // ~64.3 KB

    cudaFuncSetAttribute(k_up,   cudaFuncAttributeMaxDynamicSharedMemorySize, smem_up);
    cudaFuncSetAttribute(k_mid,  cudaFuncAttributeMaxDynamicSharedMemorySize, smem_mid);
    cudaFuncSetAttribute(k_down, cudaFuncAttributeMaxDynamicSharedMemorySize, smem_down);

    k_up<<<dim3(4, 1024), 256, smem_up>>>(x, Wup);
    k_mid<<<8192, 256, smem_mid>>>(cw, cb, Wq, Wk, Wv, igw, igb, fgw, fgb, lnw, skip);
    k_down<<<1024, 256, smem_down>>>(Wd, out);
}